// round 2
// baseline (speedup 1.0000x reference)
#include <cuda_runtime.h>
#include <math_constants.h>

// Problem constants (fixed by the dataset)
#define BATCH 4
#define NN 4096
#define MM 4096
#define KK 67              // 3 pos + 64 feat
#define KP 68              // padded K rows in packed global arrays
#define LOG2E 1.4426950408889634f

__device__ __forceinline__ float ex2f(float x) {
    float y;
    asm("ex2.approx.ftz.f32 %0, %1;" : "=f"(y) : "f"(x));
    return y;
}

// Scratch (no runtime allocation allowed) — transposed packed operands:
// g_AT[b][k][n], g_BT[b][k][m] so tile loads are coalesced and smem stores conflict-free.
__device__ float  g_AT[BATCH * KP * NN];   // ~4.5 MB
__device__ float  g_BT[BATCH * KP * MM];   // ~4.5 MB
__device__ float  g_r1[BATCH * NN];
__device__ float  g_r2[BATCH * MM];
__device__ double g_acc[BATCH];

__global__ void zero_kernel() {
    if (threadIdx.x < BATCH) g_acc[threadIdx.x] = 0.0;
}

// Pack A side: A = LOG2E * [2*pos1, -0.5*feat1]; r1 = -2*LOG2E*|p|^2 + log2(w1)
__global__ void packA_kernel(const float* __restrict__ pos1,
                             const float* __restrict__ feat1,
                             const float* __restrict__ w1) {
    int idx = blockIdx.x * blockDim.x + threadIdx.x;
    if (idx >= BATCH * NN) return;
    int b = idx / NN, n = idx % NN;
    const float* p = pos1 + (size_t)idx * 3;
    const float* f = feat1 + (size_t)idx * 64;
    float sq = p[0]*p[0] + p[1]*p[1] + p[2]*p[2];
    float* dst = g_AT + (size_t)b * KP * NN + n;
    dst[0 * NN] = LOG2E * 2.0f * p[0];
    dst[1 * NN] = LOG2E * 2.0f * p[1];
    dst[2 * NN] = LOG2E * 2.0f * p[2];
#pragma unroll
    for (int q = 0; q < 64; q++)
        dst[(size_t)(3 + q) * NN] = (-0.5f * LOG2E) * f[q];
    dst[(size_t)67 * NN] = 0.0f;
    g_r1[idx] = -2.0f * LOG2E * sq + __log2f(w1[idx]);
}

// Pack B side: B = [2*pos2, feat2]; r2 = -2*LOG2E*|p|^2 + log2(w2)
__global__ void packB_kernel(const float* __restrict__ pos2,
                             const float* __restrict__ feat2,
                             const float* __restrict__ w2) {
    int idx = blockIdx.x * blockDim.x + threadIdx.x;
    if (idx >= BATCH * MM) return;
    int b = idx / MM, m = idx % MM;
    const float* p = pos2 + (size_t)idx * 3;
    const float* f = feat2 + (size_t)idx * 64;
    float sq = p[0]*p[0] + p[1]*p[1] + p[2]*p[2];
    float* dst = g_BT + (size_t)b * KP * MM + m;
    dst[0 * MM] = 2.0f * p[0];
    dst[1 * MM] = 2.0f * p[1];
    dst[2 * MM] = 2.0f * p[2];
#pragma unroll
    for (int q = 0; q < 64; q++)
        dst[(size_t)(3 + q) * MM] = f[q];
    dst[(size_t)67 * MM] = 0.0f;
    g_r2[idx] = -2.0f * LOG2E * sq + __log2f(w2[idx]);
}

// Main: per block (n-tile of 128, batch b), sweep all M in tiles of 128.
// 256 threads as 16x16; each thread owns an 8x8 micro-tile (two 4-wide subtiles
// per dim at ty*4 and 64+ty*4 / tx*4 and 64+tx*4) -> conflict-free float4 LDS.
#define TILE 128
#define SMEM_BYTES (2 * KK * TILE * 4)

__global__ __launch_bounds__(256) void varifold_main_kernel() {
    extern __shared__ float sm[];
    float* As = sm;                 // [KK][TILE]
    float* Bs = sm + KK * TILE;     // [KK][TILE]

    const int b  = blockIdx.y;
    const int n0 = blockIdx.x * TILE;
    const int tid = threadIdx.x;
    const int tx = tid & 15;
    const int ty = tid >> 4;

    // Load A tile once (n rows fixed for this block). Coalesced; conflict-free stores.
    for (int i = tid; i < KK * TILE; i += 256) {
        int k = i >> 7, n = i & 127;
        As[i] = g_AT[((size_t)b * KP + k) * NN + n0 + n];
    }

    float r1v[8];
#pragma unroll
    for (int ii = 0; ii < 4; ii++) {
        r1v[ii]     = g_r1[b * NN + n0 +      ty * 4 + ii];
        r1v[4 + ii] = g_r1[b * NN + n0 + 64 + ty * 4 + ii];
    }

    float total = 0.0f;

    for (int mt = 0; mt < MM / TILE; ++mt) {
        const int m0 = mt * TILE;
        __syncthreads();   // previous iteration's Bs consumers done
        for (int i = tid; i < KK * TILE; i += 256) {
            int k = i >> 7, m = i & 127;
            Bs[i] = g_BT[((size_t)b * KP + k) * MM + m0 + m];
        }
        __syncthreads();

        float acc[8][8];
#pragma unroll
        for (int i = 0; i < 8; i++)
#pragma unroll
            for (int j = 0; j < 8; j++) acc[i][j] = 0.0f;

#pragma unroll 4
        for (int k = 0; k < KK; k++) {
            float4 a0 = *(const float4*)(As + k * TILE +      ty * 4);
            float4 a1 = *(const float4*)(As + k * TILE + 64 + ty * 4);
            float4 b0 = *(const float4*)(Bs + k * TILE +      tx * 4);
            float4 b1 = *(const float4*)(Bs + k * TILE + 64 + tx * 4);
            float av[8] = {a0.x, a0.y, a0.z, a0.w, a1.x, a1.y, a1.z, a1.w};
            float bv[8] = {b0.x, b0.y, b0.z, b0.w, b1.x, b1.y, b1.z, b1.w};
#pragma unroll
            for (int i = 0; i < 8; i++)
#pragma unroll
                for (int j = 0; j < 8; j++)
                    acc[i][j] = fmaf(av[i], bv[j], acc[i][j]);
        }

        float r2v[8];
#pragma unroll
        for (int jj = 0; jj < 4; jj++) {
            r2v[jj]     = g_r2[b * MM + m0 +      tx * 4 + jj];
            r2v[4 + jj] = g_r2[b * MM + m0 + 64 + tx * 4 + jj];
        }

        float tsum = 0.0f;
#pragma unroll
        for (int i = 0; i < 8; i++)
#pragma unroll
            for (int j = 0; j < 8; j++)
                tsum += ex2f(acc[i][j] + r1v[i] + r2v[j]);
        total += tsum;
    }

    // Block tree-reduction, then one double atomic per block.
    __shared__ float red[256];
    red[tid] = total;
    __syncthreads();
#pragma unroll
    for (int s = 128; s > 0; s >>= 1) {
        if (tid < s) red[tid] += red[tid + s];
        __syncthreads();
    }
    if (tid == 0) atomicAdd(&g_acc[b], (double)red[0]);
}

__global__ void finalize_kernel(float* __restrict__ out) {
    if (threadIdx.x < BATCH) out[threadIdx.x] = (float)g_acc[threadIdx.x];
}

extern "C" void kernel_launch(void* const* d_in, const int* in_sizes, int n_in,
                              void* d_out, int out_size) {
    const float* pos1  = (const float*)d_in[0];
    const float* feat1 = (const float*)d_in[1];
    const float* w1    = (const float*)d_in[2];
    const float* pos2  = (const float*)d_in[3];
    const float* feat2 = (const float*)d_in[4];
    const float* w2    = (const float*)d_in[5];
    float* out = (float*)d_out;

    cudaFuncSetAttribute(varifold_main_kernel,
                         cudaFuncAttributeMaxDynamicSharedMemorySize, SMEM_BYTES);

    zero_kernel<<<1, 32>>>();
    packA_kernel<<<(BATCH * NN + 255) / 256, 256>>>(pos1, feat1, w1);
    packB_kernel<<<(BATCH * MM + 255) / 256, 256>>>(pos2, feat2, w2);

    dim3 grid(NN / TILE, BATCH);
    varifold_main_kernel<<<grid, 256, SMEM_BYTES>>>();

    finalize_kernel<<<1, 32>>>(out);
}

// round 6
// speedup vs baseline: 1.1943x; 1.1943x over previous
#include <cuda_runtime.h>
#include <math_constants.h>

#define BATCH 4
#define NN 4096
#define MM 4096
#define KK 67              // 3 pos + 64 feat
#define KP 68
#define LOG2E 1.4426950408889634f

#define TILE 128
#define NTILES (NN / TILE)               // 32
#define MTILES (MM / TILE)               // 32
#define NJOBS (BATCH * NTILES * MTILES)  // 4096
#define NBLK 296                         // 2 CTAs/SM * 148 SMs
#define SMEM_BYTES (2 * KK * TILE * 4)

typedef unsigned long long u64;

__device__ __forceinline__ float ex2f(float x) {
    float y; asm("ex2.approx.ftz.f32 %0, %1;" : "=f"(y) : "f"(x)); return y;
}
__device__ __forceinline__ u64 fma2(u64 a, u64 b, u64 c) {
    u64 d; asm("fma.rn.f32x2 %0, %1, %2, %3;" : "=l"(d) : "l"(a), "l"(b), "l"(c)); return d;
}
__device__ __forceinline__ u64 add2(u64 a, u64 b) {
    u64 d; asm("add.rn.f32x2 %0, %1, %2;" : "=l"(d) : "l"(a), "l"(b)); return d;
}
__device__ __forceinline__ u64 pk(float lo, float hi) {
    u64 d; asm("mov.b64 %0, {%1, %2};" : "=l"(d) : "f"(lo), "f"(hi)); return d;
}
__device__ __forceinline__ void upk(u64 v, float& lo, float& hi) {
    asm("mov.b64 {%0, %1}, %2;" : "=f"(lo), "=f"(hi) : "l"(v));
}

union F4U { float4 f; u64 u[2]; };

__device__ float  g_AT[BATCH * KP * NN];   // transposed packed A: [b][k][n]
__device__ float  g_BT[BATCH * KP * MM];   // transposed packed B: [b][k][m]
__device__ float  g_r1[BATCH * NN];
__device__ float  g_r2[BATCH * MM];
__device__ double g_acc[BATCH];

__global__ void zero_kernel() {
    if (threadIdx.x < BATCH) g_acc[threadIdx.x] = 0.0;
}

// A = LOG2E * [2*pos1, -0.5*feat1]; r1 = -2*LOG2E*|p|^2 + log2(w1)
__global__ void packA_kernel(const float* __restrict__ pos1,
                             const float* __restrict__ feat1,
                             const float* __restrict__ w1) {
    int idx = blockIdx.x * blockDim.x + threadIdx.x;
    if (idx >= BATCH * NN) return;
    int b = idx / NN, n = idx % NN;
    const float* p = pos1 + (size_t)idx * 3;
    const float* f = feat1 + (size_t)idx * 64;
    float sq = p[0]*p[0] + p[1]*p[1] + p[2]*p[2];
    float* dst = g_AT + (size_t)b * KP * NN + n;
    dst[0 * NN] = LOG2E * 2.0f * p[0];
    dst[1 * NN] = LOG2E * 2.0f * p[1];
    dst[2 * NN] = LOG2E * 2.0f * p[2];
#pragma unroll
    for (int q = 0; q < 64; q++)
        dst[(size_t)(3 + q) * NN] = (-0.5f * LOG2E) * f[q];
    dst[(size_t)67 * NN] = 0.0f;
    g_r1[idx] = -2.0f * LOG2E * sq + __log2f(w1[idx]);
}

// B = [2*pos2, feat2]; r2 = -2*LOG2E*|p|^2 + log2(w2)
__global__ void packB_kernel(const float* __restrict__ pos2,
                             const float* __restrict__ feat2,
                             const float* __restrict__ w2) {
    int idx = blockIdx.x * blockDim.x + threadIdx.x;
    if (idx >= BATCH * MM) return;
    int b = idx / MM, m = idx % MM;
    const float* p = pos2 + (size_t)idx * 3;
    const float* f = feat2 + (size_t)idx * 64;
    float sq = p[0]*p[0] + p[1]*p[1] + p[2]*p[2];
    float* dst = g_BT + (size_t)b * KP * MM + m;
    dst[0 * MM] = 2.0f * p[0];
    dst[1 * MM] = 2.0f * p[1];
    dst[2 * MM] = 2.0f * p[2];
#pragma unroll
    for (int q = 0; q < 64; q++)
        dst[(size_t)(3 + q) * MM] = f[q];
    dst[(size_t)67 * MM] = 0.0f;
    g_r2[idx] = -2.0f * LOG2E * sq + __log2f(w2[idx]);
}

// Persistent-chunk main kernel: 296 blocks, each takes a contiguous range of the
// 4096 (b, n-tile, m-tile) jobs ordered m-fastest (As tile reloads <= 2/block).
// 256 threads as 16x16; 8x8 micro-tile per thread; accumulators packed as f32x2
// along i (a-pairs come free from the float4 A-fragments).
__global__ __launch_bounds__(256, 2) void varifold_main_kernel() {
    extern __shared__ float sm[];
    float* As = sm;                 // [KK][TILE]
    float* Bs = sm + KK * TILE;     // [KK][TILE]

    const int tid = threadIdx.x;
    const int tx = tid & 15;
    const int ty = tid >> 4;

    const int jstart = (int)(((long long)blockIdx.x * NJOBS) / NBLK);
    const int jend   = (int)(((long long)(blockIdx.x + 1) * NJOBS) / NBLK);

    int cur_bn = -1;
    u64 r1p[4];                     // packed r1 pairs, matches acc i-pairs
    float btotal[BATCH];
#pragma unroll
    for (int i = 0; i < BATCH; i++) btotal[i] = 0.0f;

    for (int job = jstart; job < jend; ++job) {
        const int b  = job >> 10;
        const int nt = (job >> 5) & 31;
        const int mt = job & 31;
        const int bn = job >> 5;
        const int n0 = nt * TILE;
        const int m0 = mt * TILE;

        __syncthreads();            // previous job's smem consumers done
        if (bn != cur_bn) {
            for (int i = tid; i < KK * TILE; i += 256) {
                int k = i >> 7, n = i & 127;
                As[i] = g_AT[((size_t)b * KP + k) * NN + n0 + n];
            }
            float r1v[8];
#pragma unroll
            for (int ii = 0; ii < 4; ii++) {
                r1v[ii]     = g_r1[b * NN + n0 +      ty * 4 + ii];
                r1v[4 + ii] = g_r1[b * NN + n0 + 64 + ty * 4 + ii];
            }
            r1p[0] = pk(r1v[0], r1v[1]);
            r1p[1] = pk(r1v[2], r1v[3]);
            r1p[2] = pk(r1v[4], r1v[5]);
            r1p[3] = pk(r1v[6], r1v[7]);
            cur_bn = bn;
        }
        for (int i = tid; i < KK * TILE; i += 256) {
            int k = i >> 7, m = i & 127;
            Bs[i] = g_BT[((size_t)b * KP + k) * MM + m0 + m];
        }
        __syncthreads();

        u64 acc[4][8];              // [i-pair][j], each holds 2 fp32 accumulators
#pragma unroll
        for (int i = 0; i < 4; i++)
#pragma unroll
            for (int j = 0; j < 8; j++) acc[i][j] = 0ULL;

#pragma unroll 2
        for (int k = 0; k < KK; k++) {
            F4U a0, a1, b0, b1;
            a0.f = *(const float4*)(As + k * TILE +      ty * 4);
            a1.f = *(const float4*)(As + k * TILE + 64 + ty * 4);
            b0.f = *(const float4*)(Bs + k * TILE +      tx * 4);
            b1.f = *(const float4*)(Bs + k * TILE + 64 + tx * 4);
            u64 a2[4] = {a0.u[0], a0.u[1], a1.u[0], a1.u[1]};
            u64 bd[8];
            bd[0] = pk(b0.f.x, b0.f.x); bd[1] = pk(b0.f.y, b0.f.y);
            bd[2] = pk(b0.f.z, b0.f.z); bd[3] = pk(b0.f.w, b0.f.w);
            bd[4] = pk(b1.f.x, b1.f.x); bd[5] = pk(b1.f.y, b1.f.y);
            bd[6] = pk(b1.f.z, b1.f.z); bd[7] = pk(b1.f.w, b1.f.w);
#pragma unroll
            for (int j = 0; j < 8; j++)
#pragma unroll
                for (int i = 0; i < 4; i++)
                    acc[i][j] = fma2(a2[i], bd[j], acc[i][j]);
        }

        // epilogue: arg = acc + r1 + r2 (packed adds), scalar EX2 + sum
        float r2v[8];
#pragma unroll
        for (int jj = 0; jj < 4; jj++) {
            r2v[jj]     = g_r2[b * MM + m0 +      tx * 4 + jj];
            r2v[4 + jj] = g_r2[b * MM + m0 + 64 + tx * 4 + jj];
        }
        float tsum = 0.0f;
#pragma unroll
        for (int j = 0; j < 8; j++) {
            u64 r2d = pk(r2v[j], r2v[j]);
#pragma unroll
            for (int i = 0; i < 4; i++) {
                u64 arg = add2(add2(acc[i][j], r1p[i]), r2d);
                float lo, hi; upk(arg, lo, hi);
                tsum += ex2f(lo) + ex2f(hi);
            }
        }
        btotal[b] += tsum;
    }

    // per-batch block reduction; skip batches this block never touched
    __shared__ float red[256];
#pragma unroll
    for (int bb = 0; bb < BATCH; bb++) {
        __syncthreads();
        red[tid] = btotal[bb];
        __syncthreads();
#pragma unroll
        for (int s = 128; s > 0; s >>= 1) {
            if (tid < s) red[tid] += red[tid + s];
            __syncthreads();
        }
        if (tid == 0 && red[0] != 0.0f) atomicAdd(&g_acc[bb], (double)red[0]);
    }
}

__global__ void finalize_kernel(float* __restrict__ out) {
    if (threadIdx.x < BATCH) out[threadIdx.x] = (float)g_acc[threadIdx.x];
}

extern "C" void kernel_launch(void* const* d_in, const int* in_sizes, int n_in,
                              void* d_out, int out_size) {
    const float* pos1  = (const float*)d_in[0];
    const float* feat1 = (const float*)d_in[1];
    const float* w1    = (const float*)d_in[2];
    const float* pos2  = (const float*)d_in[3];
    const float* feat2 = (const float*)d_in[4];
    const float* w2    = (const float*)d_in[5];
    float* out = (float*)d_out;

    cudaFuncSetAttribute(varifold_main_kernel,
                         cudaFuncAttributeMaxDynamicSharedMemorySize, SMEM_BYTES);

    zero_kernel<<<1, 32>>>();
    packA_kernel<<<(BATCH * NN + 255) / 256, 256>>>(pos1, feat1, w1);
    packB_kernel<<<(BATCH * MM + 255) / 256, 256>>>(pos2, feat2, w2);

    varifold_main_kernel<<<NBLK, 256, SMEM_BYTES>>>();

    finalize_kernel<<<1, 32>>>(out);
}

// round 10
// speedup vs baseline: 3.0482x; 2.5522x over previous
#include <cuda_runtime.h>
#include <cuda_bf16.h>
#include <cstdint>

#define BATCH 4
#define NN 4096
#define MM 4096
#define KF 67                  // 3 pos + 64 feat
#define KSEG 201               // [s0(67) | s1(67) | s2(67)]
#define KCOLS 216              // padded row length (432 B) -> conflict-free ldmatrix
#define ROWB 432               // row stride bytes
#define KCHUNK 13              // 13 * 16 = 208 >= 201 (cols 201..215 zero)
#define LOG2E 1.4426950408889634f

#define TILE 128
#define NT 32
#define MT 32
#define NJOBS (BATCH * NT * MT)      // 4096
#define NBLK 296
#define TILE_B (TILE * ROWB)         // 55296 bytes per packed tile
#define TILE_CHUNKS (TILE_B / 16)    // 3456

// smem layout (bytes)
#define SM_AS   0
#define SM_BS   (SM_AS + TILE_B)      // 55296
#define SM_R1   (SM_BS + TILE_B)      // 110592
#define SM_R2   (SM_R1 + 512)         // 111104
#define SM_RED  (SM_R2 + 512)         // 111616
#define SM_TOT  (SM_RED + 1024)       // 112640  (x2 CTAs = 225280 <= 228KB/SM)

// ---------------- helpers ----------------
__device__ __forceinline__ float ex2f(float x) {
    float y; asm("ex2.approx.ftz.f32 %0, %1;" : "=f"(y) : "f"(x)); return y;
}
__device__ __forceinline__ uint32_t smem_u32(const void* p) {
    uint32_t a;
    asm("{ .reg .u64 t; cvta.to.shared.u64 t, %1; cvt.u32.u64 %0, t; }" : "=r"(a) : "l"(p));
    return a;
}
__device__ __forceinline__ void cp16(uint32_t dst, const void* src) {
    asm volatile("cp.async.cg.shared.global [%0], [%1], 16;" :: "r"(dst), "l"(src) : "memory");
}
__device__ __forceinline__ void cp_commit_wait() {
    asm volatile("cp.async.commit_group;" ::: "memory");
    asm volatile("cp.async.wait_group 0;" ::: "memory");
}
__device__ __forceinline__ void ldsm4(uint32_t* r, uint32_t a) {
    asm volatile("ldmatrix.sync.aligned.m8n8.x4.shared.b16 {%0,%1,%2,%3}, [%4];"
                 : "=r"(r[0]), "=r"(r[1]), "=r"(r[2]), "=r"(r[3]) : "r"(a));
}
__device__ __forceinline__ void ldsm2(uint32_t* r, uint32_t a) {
    asm volatile("ldmatrix.sync.aligned.m8n8.x2.shared.b16 {%0,%1}, [%2];"
                 : "=r"(r[0]), "=r"(r[1]) : "r"(a));
}
__device__ __forceinline__ void mma_bf16(float* d, const uint32_t* a, const uint32_t* b) {
    asm volatile(
        "mma.sync.aligned.m16n8k16.row.col.f32.bf16.bf16.f32 "
        "{%0,%1,%2,%3}, {%4,%5,%6,%7}, {%8,%9}, {%0,%1,%2,%3};"
        : "+f"(d[0]), "+f"(d[1]), "+f"(d[2]), "+f"(d[3])
        : "r"(a[0]), "r"(a[1]), "r"(a[2]), "r"(a[3]), "r"(b[0]), "r"(b[1]));
}

// ---------------- global scratch ----------------
__device__ __align__(128) unsigned char g_A2[BATCH * NT * TILE_B];  // ~7 MB
__device__ __align__(128) unsigned char g_B2[BATCH * MT * TILE_B];  // ~7 MB
__device__ float  g_r1[BATCH * NN];
__device__ float  g_r2[BATCH * MM];
__device__ double g_acc[BATCH];

__global__ void zero_kernel() {
    if (threadIdx.x < BATCH) g_acc[threadIdx.x] = 0.0;
}

// Write one packed bf16 row: 216 cols = 27 x 16B units.
// IS_A: segments [hi, lo, hi]; else [hi, hi, lo]   (lo = bf16(x - bf16(x)))
template <bool IS_A>
__device__ __forceinline__ void write_row(unsigned char* rowp, const float* a) {
#pragma unroll
    for (int u = 0; u < 27; u++) {
        uint4 val;
        unsigned short* hp = (unsigned short*)&val;
#pragma unroll
        for (int e = 0; e < 8; e++) {
            int c = u * 8 + e;
            __nv_bfloat16 v = __float2bfloat16(0.0f);
            if (c < KSEG) {
                int seg = (c >= 2 * KF) ? 2 : (c >= KF ? 1 : 0);
                float x = a[c - seg * KF];
                __nv_bfloat16 h1 = __float2bfloat16(x);
                bool residual = IS_A ? (seg == 1) : (seg == 2);
                v = residual ? __float2bfloat16(x - __bfloat162float(h1)) : h1;
            }
            hp[e] = *(unsigned short*)&v;
        }
        *(uint4*)(rowp + u * 16) = val;
    }
}

__global__ void packA_kernel(const float* __restrict__ pos1,
                             const float* __restrict__ feat1,
                             const float* __restrict__ w1) {
    int idx = blockIdx.x * blockDim.x + threadIdx.x;
    if (idx >= BATCH * NN) return;
    int b = idx / NN, n = idx % NN;
    const float* p = pos1 + (size_t)idx * 3;
    const float* f = feat1 + (size_t)idx * 64;
    float a[KF];
    a[0] = 2.0f * LOG2E * p[0];
    a[1] = 2.0f * LOG2E * p[1];
    a[2] = 2.0f * LOG2E * p[2];
#pragma unroll
    for (int q = 0; q < 64; q++) a[3 + q] = (-0.5f * LOG2E) * f[q];
    float sq = p[0]*p[0] + p[1]*p[1] + p[2]*p[2];
    g_r1[idx] = -2.0f * LOG2E * sq + __log2f(w1[idx]);
    int nt = n >> 7, row = n & 127;
    write_row<true>(g_A2 + (size_t)(b * NT + nt) * TILE_B + (size_t)row * ROWB, a);
}

__global__ void packB_kernel(const float* __restrict__ pos2,
                             const float* __restrict__ feat2,
                             const float* __restrict__ w2) {
    int idx = blockIdx.x * blockDim.x + threadIdx.x;
    if (idx >= BATCH * MM) return;
    int b = idx / MM, m = idx % MM;
    const float* p = pos2 + (size_t)idx * 3;
    const float* f = feat2 + (size_t)idx * 64;
    float a[KF];
    a[0] = 2.0f * p[0];
    a[1] = 2.0f * p[1];
    a[2] = 2.0f * p[2];
#pragma unroll
    for (int q = 0; q < 64; q++) a[3 + q] = f[q];
    float sq = p[0]*p[0] + p[1]*p[1] + p[2]*p[2];
    g_r2[idx] = -2.0f * LOG2E * sq + __log2f(w2[idx]);
    int mt = m >> 7, row = m & 127;
    write_row<false>(g_B2 + (size_t)(b * MT + mt) * TILE_B + (size_t)row * ROWB, a);
}

// ---------------- main HMMA kernel ----------------
// 296 persistent CTAs (2/SM), 256 threads = 8 warps (2 m-halves x 4 n-quarters).
// Warp tile 64x32; mma.sync m16n8k16 bf16; A tile cached per (b,nt).
__global__ __launch_bounds__(256, 2) void varifold_hmma_kernel() {
    extern __shared__ unsigned char smem[];
    const uint32_t sb = smem_u32(smem);
    float* r1s = (float*)(smem + SM_R1);
    float* r2s = (float*)(smem + SM_R2);
    float* red = (float*)(smem + SM_RED);

    const int tid  = threadIdx.x;
    const int lane = tid & 31;
    const int w    = tid >> 5;
    const int wm   = w & 1;        // m-half: rows wm*64..+63
    const int wn   = w >> 1;       // n-quarter: cols wn*32..+31

    // per-thread ldmatrix base offsets
    const uint32_t a_base = sb + SM_AS
        + (uint32_t)(wm * 64 + (lane & 7) + ((lane >> 3) & 1) * 8) * ROWB
        + ((lane >> 4) & 1) * 16;
    const int l2 = lane & 15;
    const uint32_t b_base = sb + SM_BS
        + (uint32_t)(wn * 32 + (l2 & 7)) * ROWB
        + ((l2 >> 3) & 1) * 16;

    const int jstart = (int)(((long long)blockIdx.x * NJOBS) / NBLK);
    const int jend   = (int)(((long long)(blockIdx.x + 1) * NJOBS) / NBLK);

    int cur_bn = -1;
    float bt0 = 0.0f, bt1 = 0.0f, bt2 = 0.0f, bt3 = 0.0f;

    for (int job = jstart; job < jend; ++job) {
        const int b  = job >> 10;
        const int nt = (job >> 5) & 31;
        const int mt = job & 31;
        const int bn = job >> 5;
        const int n0 = nt * TILE;
        const int m0 = mt * TILE;

        __syncthreads();           // previous tile's smem consumers done
        if (bn != cur_bn) {
            const unsigned char* src = g_A2 + (size_t)(b * NT + nt) * TILE_B;
            for (int i = tid; i < TILE_CHUNKS; i += 256)
                cp16(sb + SM_AS + i * 16, src + (size_t)i * 16);
            if (tid < 32) cp16(sb + SM_R1 + tid * 16, g_r1 + b * NN + n0 + tid * 4);
            cur_bn = bn;
        }
        {
            const unsigned char* src = g_B2 + (size_t)(b * MT + mt) * TILE_B;
            for (int i = tid; i < TILE_CHUNKS; i += 256)
                cp16(sb + SM_BS + i * 16, src + (size_t)i * 16);
            if (tid < 32) cp16(sb + SM_R2 + tid * 16, g_r2 + b * MM + m0 + tid * 4);
        }
        cp_commit_wait();
        __syncthreads();

        float acc[4][4][4];
#pragma unroll
        for (int mi = 0; mi < 4; mi++)
#pragma unroll
            for (int ni = 0; ni < 4; ni++)
#pragma unroll
                for (int q = 0; q < 4; q++) acc[mi][ni][q] = 0.0f;

#pragma unroll 1
        for (int kc = 0; kc < KCHUNK; kc++) {
            uint32_t af[4][4], bf[4][2];
#pragma unroll
            for (int mi = 0; mi < 4; mi++)
                ldsm4(af[mi], a_base + mi * (16 * ROWB) + kc * 32);
#pragma unroll
            for (int ni = 0; ni < 4; ni++)
                ldsm2(bf[ni], b_base + ni * (8 * ROWB) + kc * 32);
#pragma unroll
            for (int mi = 0; mi < 4; mi++)
#pragma unroll
                for (int ni = 0; ni < 4; ni++)
                    mma_bf16(acc[mi][ni], af[mi], bf[ni]);
        }

        // epilogue: d + r1[row] + r2[col] -> exp2, accumulate
        const int r0 = wm * 64 + (lane >> 2);
        const int c0 = wn * 32 + 2 * (lane & 3);
        float ts = 0.0f;
#pragma unroll
        for (int mi = 0; mi < 4; mi++) {
            float r1a = r1s[r0 + mi * 16];
            float r1b = r1s[r0 + mi * 16 + 8];
#pragma unroll
            for (int ni = 0; ni < 4; ni++) {
                float r2a = r2s[c0 + ni * 8];
                float r2b = r2s[c0 + ni * 8 + 1];
                ts += ex2f(acc[mi][ni][0] + r1a + r2a);
                ts += ex2f(acc[mi][ni][1] + r1a + r2b);
                ts += ex2f(acc[mi][ni][2] + r1b + r2a);
                ts += ex2f(acc[mi][ni][3] + r1b + r2b);
            }
        }
        if      (b == 0) bt0 += ts;
        else if (b == 1) bt1 += ts;
        else if (b == 2) bt2 += ts;
        else             bt3 += ts;
    }

    // per-batch block reduction, one double atomic per touched batch
#pragma unroll
    for (int bb = 0; bb < BATCH; bb++) {
        float v = (bb == 0) ? bt0 : (bb == 1) ? bt1 : (bb == 2) ? bt2 : bt3;
        __syncthreads();
        red[tid] = v;
        __syncthreads();
#pragma unroll
        for (int s = 128; s > 0; s >>= 1) {
            if (tid < s) red[tid] += red[tid + s];
            __syncthreads();
        }
        if (tid == 0 && red[0] != 0.0f) atomicAdd(&g_acc[bb], (double)red[0]);
    }
}

__global__ void finalize_kernel(float* __restrict__ out) {
    if (threadIdx.x < BATCH) out[threadIdx.x] = (float)g_acc[threadIdx.x];
}

extern "C" void kernel_launch(void* const* d_in, const int* in_sizes, int n_in,
                              void* d_out, int out_size) {
    const float* pos1  = (const float*)d_in[0];
    const float* feat1 = (const float*)d_in[1];
    const float* w1    = (const float*)d_in[2];
    const float* pos2  = (const float*)d_in[3];
    const float* feat2 = (const float*)d_in[4];
    const float* w2    = (const float*)d_in[5];
    float* out = (float*)d_out;

    cudaFuncSetAttribute(varifold_hmma_kernel,
                         cudaFuncAttributeMaxDynamicSharedMemorySize, SM_TOT);

    zero_kernel<<<1, 32>>>();
    packA_kernel<<<(BATCH * NN + 127) / 128, 128>>>(pos1, feat1, w1);
    packB_kernel<<<(BATCH * MM + 127) / 128, 128>>>(pos2, feat2, w2);

    varifold_hmma_kernel<<<NBLK, 256, SM_TOT>>>();

    finalize_kernel<<<1, 32>>>(out);
}

// round 11
// speedup vs baseline: 3.1240x; 1.0249x over previous
#include <cuda_runtime.h>
#include <cuda_bf16.h>
#include <cstdint>

#define BATCH 4
#define NN 4096
#define MM 4096
#define KF 67                  // 3 pos + 64 feat
#define KSEG 201               // [s0(67) | s1(67) | s2(67)]
#define ROWB 432               // row stride bytes (216 bf16 cols) -> conflict-free ldmatrix
#define KCHUNK 13              // 13 * 16 = 208 >= 201 (cols 201..215 zero)
#define LOG2E 1.4426950408889634f

#define TILE 128
#define NT 32
#define MT 32
#define NJOBS (BATCH * NT * MT)      // 4096
#define NBLK 148                     // 1 persistent CTA per SM
#define TILE_B (TILE * ROWB)         // 55296 bytes per packed tile
#define TILE_CHUNKS (TILE_B / 16)    // 3456

// smem layout (bytes)
#define SM_A    0
#define SM_B0   (SM_A + TILE_B)       // 55296
#define SM_B1   (SM_B0 + TILE_B)      // 110592
#define SM_R1   (SM_B1 + TILE_B)      // 165888
#define SM_R20  (SM_R1 + 512)         // 166400
#define SM_R21  (SM_R20 + 512)        // 166912
#define SM_RED  (SM_R21 + 512)        // 167424
#define SM_TOT  (SM_RED + 1024)       // 168448  (1 CTA/SM)

// ---------------- helpers ----------------
__device__ __forceinline__ float ex2f(float x) {
    float y; asm("ex2.approx.ftz.f32 %0, %1;" : "=f"(y) : "f"(x)); return y;
}
__device__ __forceinline__ uint32_t smem_u32(const void* p) {
    uint32_t a;
    asm("{ .reg .u64 t; cvta.to.shared.u64 t, %1; cvt.u32.u64 %0, t; }" : "=r"(a) : "l"(p));
    return a;
}
__device__ __forceinline__ void cp16(uint32_t dst, const void* src) {
    asm volatile("cp.async.cg.shared.global [%0], [%1], 16;" :: "r"(dst), "l"(src) : "memory");
}
__device__ __forceinline__ void cp_commit() {
    asm volatile("cp.async.commit_group;" ::: "memory");
}
__device__ __forceinline__ void cp_wait1() {
    asm volatile("cp.async.wait_group 1;" ::: "memory");
}
__device__ __forceinline__ void ldsm4(uint32_t* r, uint32_t a) {
    asm volatile("ldmatrix.sync.aligned.m8n8.x4.shared.b16 {%0,%1,%2,%3}, [%4];"
                 : "=r"(r[0]), "=r"(r[1]), "=r"(r[2]), "=r"(r[3]) : "r"(a));
}
__device__ __forceinline__ void ldsm2(uint32_t* r, uint32_t a) {
    asm volatile("ldmatrix.sync.aligned.m8n8.x2.shared.b16 {%0,%1}, [%2];"
                 : "=r"(r[0]), "=r"(r[1]) : "r"(a));
}
__device__ __forceinline__ void mma_bf16(float* d, const uint32_t* a, const uint32_t* b) {
    asm volatile(
        "mma.sync.aligned.m16n8k16.row.col.f32.bf16.bf16.f32 "
        "{%0,%1,%2,%3}, {%4,%5,%6,%7}, {%8,%9}, {%0,%1,%2,%3};"
        : "+f"(d[0]), "+f"(d[1]), "+f"(d[2]), "+f"(d[3])
        : "r"(a[0]), "r"(a[1]), "r"(a[2]), "r"(a[3]), "r"(b[0]), "r"(b[1]));
}

// ---------------- global scratch ----------------
__device__ __align__(128) unsigned char g_A2[BATCH * NT * TILE_B];  // ~7 MB
__device__ __align__(128) unsigned char g_B2[BATCH * MT * TILE_B];  // ~7 MB
__device__ float  g_r1[BATCH * NN];
__device__ float  g_r2[BATCH * MM];
__device__ double g_acc[BATCH];

__global__ void zero_kernel() {
    if (threadIdx.x < BATCH) g_acc[threadIdx.x] = 0.0;
}

// ---------------- pack kernels: warp-per-row, coalesced 432B row stores ----------
// IS_A: segments [hi, lo, hi]; else [hi, hi, lo]   (lo = bf16(x - bf16(x)))
template <bool IS_A>
__global__ void pack_kernel(const float* __restrict__ pos,
                            const float* __restrict__ feat,
                            const float* __restrict__ wgt) {
    int gw   = (blockIdx.x * blockDim.x + threadIdx.x) >> 5;  // row index
    int lane = threadIdx.x & 31;
    if (gw >= BATCH * NN) return;
    int b = gw >> 12, n = gw & 4095;

    const float* p = pos + (size_t)gw * 3;
    const float* f = feat + (size_t)gw * 64;

    unsigned char* base = (IS_A ? g_A2 : g_B2);
    unsigned char* rowp = base + (size_t)(b * NT + (n >> 7)) * TILE_B + (size_t)(n & 127) * ROWB;

    if (lane < 27) {
        uint4 val;
        unsigned short* hp = (unsigned short*)&val;
#pragma unroll
        for (int e = 0; e < 8; e++) {
            int c = lane * 8 + e;
            __nv_bfloat16 v = __float2bfloat16(0.0f);
            if (c < KSEG) {
                int seg = (c >= 2 * KF) ? 2 : (c >= KF ? 1 : 0);
                int i = c - seg * KF;
                float x;
                if (IS_A) x = (i < 3) ? (2.0f * LOG2E) * p[i] : (-0.5f * LOG2E) * f[i - 3];
                else      x = (i < 3) ? 2.0f * p[i] : f[i - 3];
                __nv_bfloat16 h1 = __float2bfloat16(x);
                bool residual = IS_A ? (seg == 1) : (seg == 2);
                v = residual ? __float2bfloat16(x - __bfloat162float(h1)) : h1;
            }
            hp[e] = *(unsigned short*)&v;
        }
        *(uint4*)(rowp + lane * 16) = val;
    } else if (lane == 27) {
        float sq = p[0]*p[0] + p[1]*p[1] + p[2]*p[2];
        float r = -2.0f * LOG2E * sq + __log2f(wgt[gw]);
        if (IS_A) g_r1[gw] = r; else g_r2[gw] = r;
    }
}

// ---------------- main HMMA kernel (software pipelined) ----------------
// 148 persistent CTAs (1/SM), 256 threads = 8 warps (2 m-halves x 4 n-quarters).
// Warp tile 64x32; mma.sync m16n8k16 bf16; B tiles double-buffered via cp.async.
__global__ __launch_bounds__(256, 1) void varifold_hmma_kernel() {
    extern __shared__ unsigned char smem[];
    const uint32_t sb = smem_u32(smem);
    float* r1s = (float*)(smem + SM_R1);
    float* red = (float*)(smem + SM_RED);

    const int tid  = threadIdx.x;
    const int lane = tid & 31;
    const int w    = tid >> 5;
    const int wm   = w & 1;        // m-half: rows wm*64..+63
    const int wn   = w >> 1;       // n-quarter: cols wn*32..+31

    // per-thread ldmatrix offsets (relative to tile base)
    const uint32_t a_rel = (uint32_t)(wm * 64 + (lane & 7) + ((lane >> 3) & 1) * 8) * ROWB
                         + ((lane >> 4) & 1) * 16;
    const int l2 = lane & 15;
    const uint32_t b_rel = (uint32_t)(wn * 32 + (l2 & 7)) * ROWB + ((l2 >> 3) & 1) * 16;

    const int jstart = (int)(((long long)blockIdx.x * NJOBS) / NBLK);
    const int jend   = (int)(((long long)(blockIdx.x + 1) * NJOBS) / NBLK);
    if (jstart >= jend) return;

    float bt0 = 0.0f, bt1 = 0.0f, bt2 = 0.0f, bt3 = 0.0f;

    // ---- prologue: load A(jstart), r1, B(jstart), r2 as one cp.async group ----
    {
        const int j = jstart;
        const int bn = j >> 5;               // b*32 + nt
        const int bm = ((j >> 10) << 5) | (j & 31);  // b*32 + mt
        const unsigned char* asrc = g_A2 + (size_t)bn * TILE_B;
        const unsigned char* bsrc = g_B2 + (size_t)bm * TILE_B;
        uint32_t bbuf = (j & 1) ? SM_B1 : SM_B0;
        uint32_t rbuf = (j & 1) ? SM_R21 : SM_R20;
        for (int i = tid; i < TILE_CHUNKS; i += 256) {
            cp16(sb + SM_A + i * 16, asrc + (size_t)i * 16);
            cp16(sb + bbuf + i * 16, bsrc + (size_t)i * 16);
        }
        if (tid < 32) {
            cp16(sb + SM_R1 + tid * 16, g_r1 + bn * 128 + tid * 4);
            cp16(sb + rbuf + tid * 16, g_r2 + bm * 128 + tid * 4);
        }
        cp_commit();
    }

    for (int j = jstart; j < jend; ++j) {
        const int s  = j & 1;
        const int b  = j >> 10;
        const int bn = j >> 5;
        const bool nextSame = (j + 1 < jend) && (((j + 1) >> 5) == bn);

        __syncthreads();   // all warps done with job j-1 (buffer s^1 free)

        if (nextSame) {
            const int j1 = j + 1;
            const int bm1 = ((j1 >> 10) << 5) | (j1 & 31);
            const unsigned char* bsrc = g_B2 + (size_t)bm1 * TILE_B;
            uint32_t bbuf = (j1 & 1) ? SM_B1 : SM_B0;
            uint32_t rbuf = (j1 & 1) ? SM_R21 : SM_R20;
            for (int i = tid; i < TILE_CHUNKS; i += 256)
                cp16(sb + bbuf + i * 16, bsrc + (size_t)i * 16);
            if (tid < 32)
                cp16(sb + rbuf + tid * 16, g_r2 + bm1 * 128 + tid * 4);
        }
        cp_commit();       // group for j+1 (possibly empty)
        cp_wait1();        // group for j retired
        __syncthreads();   // publish B(j)

        // ---- compute job j ----
        const uint32_t a_base = sb + SM_A + a_rel;
        const uint32_t b_base = sb + (s ? SM_B1 : SM_B0) + b_rel;
        const float* r2s = (const float*)(smem + (s ? SM_R21 : SM_R20));

        float acc[4][4][4];
#pragma unroll
        for (int mi = 0; mi < 4; mi++)
#pragma unroll
            for (int ni = 0; ni < 4; ni++)
#pragma unroll
                for (int q = 0; q < 4; q++) acc[mi][ni][q] = 0.0f;

#pragma unroll 1
        for (int kc = 0; kc < KCHUNK; kc++) {
            uint32_t af[4][4], bf[4][2];
#pragma unroll
            for (int mi = 0; mi < 4; mi++)
                ldsm4(af[mi], a_base + mi * (16 * ROWB) + kc * 32);
#pragma unroll
            for (int ni = 0; ni < 4; ni++)
                ldsm2(bf[ni], b_base + ni * (8 * ROWB) + kc * 32);
#pragma unroll
            for (int mi = 0; mi < 4; mi++)
#pragma unroll
                for (int ni = 0; ni < 4; ni++)
                    mma_bf16(acc[mi][ni], af[mi], bf[ni]);
        }

        // epilogue: d + r1[row] + r2[col] -> exp2; 4 partial sums to break chains
        const int r0 = wm * 64 + (lane >> 2);
        const int c0 = wn * 32 + 2 * (lane & 3);
        float t0 = 0.0f, t1 = 0.0f, t2 = 0.0f, t3 = 0.0f;
#pragma unroll
        for (int mi = 0; mi < 4; mi++) {
            float r1a = r1s[r0 + mi * 16];
            float r1b = r1s[r0 + mi * 16 + 8];
#pragma unroll
            for (int ni = 0; ni < 4; ni++) {
                float r2a = r2s[c0 + ni * 8];
                float r2b = r2s[c0 + ni * 8 + 1];
                t0 += ex2f(acc[mi][ni][0] + r1a + r2a);
                t1 += ex2f(acc[mi][ni][1] + r1a + r2b);
                t2 += ex2f(acc[mi][ni][2] + r1b + r2a);
                t3 += ex2f(acc[mi][ni][3] + r1b + r2b);
            }
        }
        float ts = (t0 + t1) + (t2 + t3);
        if      (b == 0) bt0 += ts;
        else if (b == 1) bt1 += ts;
        else if (b == 2) bt2 += ts;
        else             bt3 += ts;

        // ---- A changes at j+1: flush pipeline and reload A + B(j+1) ----
        if (!nextSame && j + 1 < jend) {
            __syncthreads();   // all warps done reading A
            const int j1 = j + 1;
            const int bn1 = j1 >> 5;
            const int bm1 = ((j1 >> 10) << 5) | (j1 & 31);
            const unsigned char* asrc = g_A2 + (size_t)bn1 * TILE_B;
            const unsigned char* bsrc = g_B2 + (size_t)bm1 * TILE_B;
            uint32_t bbuf = (j1 & 1) ? SM_B1 : SM_B0;
            uint32_t rbuf = (j1 & 1) ? SM_R21 : SM_R20;
            for (int i = tid; i < TILE_CHUNKS; i += 256) {
                cp16(sb + SM_A + i * 16, asrc + (size_t)i * 16);
                cp16(sb + bbuf + i * 16, bsrc + (size_t)i * 16);
            }
            if (tid < 32) {
                cp16(sb + SM_R1 + tid * 16, g_r1 + bn1 * 128 + tid * 4);
                cp16(sb + rbuf + tid * 16, g_r2 + bm1 * 128 + tid * 4);
            }
            cp_commit();
        }
    }

    // per-batch block reduction, one double atomic per touched batch
#pragma unroll
    for (int bb = 0; bb < BATCH; bb++) {
        float v = (bb == 0) ? bt0 : (bb == 1) ? bt1 : (bb == 2) ? bt2 : bt3;
        __syncthreads();
        red[tid] = v;
        __syncthreads();
#pragma unroll
        for (int st = 128; st > 0; st >>= 1) {
            if (tid < st) red[tid] += red[tid + st];
            __syncthreads();
        }
        if (tid == 0 && red[0] != 0.0f) atomicAdd(&g_acc[bb], (double)red[0]);
    }
}

__global__ void finalize_kernel(float* __restrict__ out) {
    if (threadIdx.x < BATCH) out[threadIdx.x] = (float)g_acc[threadIdx.x];
}

extern "C" void kernel_launch(void* const* d_in, const int* in_sizes, int n_in,
                              void* d_out, int out_size) {
    const float* pos1  = (const float*)d_in[0];
    const float* feat1 = (const float*)d_in[1];
    const float* w1    = (const float*)d_in[2];
    const float* pos2  = (const float*)d_in[3];
    const float* feat2 = (const float*)d_in[4];
    const float* w2    = (const float*)d_in[5];
    float* out = (float*)d_out;

    cudaFuncSetAttribute(varifold_hmma_kernel,
                         cudaFuncAttributeMaxDynamicSharedMemorySize, SM_TOT);

    zero_kernel<<<1, 32>>>();
    // 8 rows per 256-thread block
    pack_kernel<true><<<(BATCH * NN) / 8, 256>>>(pos1, feat1, w1);
    pack_kernel<false><<<(BATCH * MM) / 8, 256>>>(pos2, feat2, w2);

    varifold_hmma_kernel<<<NBLK, 256, SM_TOT>>>();

    finalize_kernel<<<1, 32>>>(out);
}